// round 11
// baseline (speedup 1.0000x reference)
#include <cuda_runtime.h>
#include <math.h>
#include <stdint.h>

// ---------------------------------------------------------------------------
// ImportanceRenderer: smem-param gather + scalar-FFMA MLP (sm_100a-friendly).
//  K0: transpose planes (B,3,32,256,256) -> channel-last
//  K1: coarse eval + fused importance sampling
//  K2: fine eval + fused merge + final 96-sample ray march
// Block = 192 threads = 6 warps = 4 rays x 48 samples.
// ---------------------------------------------------------------------------

#define B_N 2
#define R_N 4096
#define SC 48
#define SF 48
#define NRAY (B_N * R_N)        // 8192
#define NSAMP (NRAY * SC)       // 393216
#define CPL 32
#define HPX 256
#define HID 64
#define CRGB 32
#define PLSTRIDE (HPX * HPX * CPL)

#define RAY_START_F 2.25f
#define DELTA_F (1.05f / 47.0f)

#define OFF_DEPTH (NRAY * CRGB)         // 262144
#define OFF_WSUM  (OFF_DEPTH + NRAY)    // 270336
#define OFF_SDF   (OFF_WSUM + NRAY)     // 278528

#define BUFS 40   // s_buf row stride (160B, 16B-aligned rows)

// Dynamic smem layout (float offsets); all regions 16B aligned
#define SM_BUF   0                      // 192*40 = 7680
#define SM_GP    7680                   // 192*24 = 4608 -> 12288
#define SM_W1T   12288                  // 64*32  = 2048 -> 14336  (w1/3, j-major)
#define SM_W2    14336                  // 64*36  = 2304 -> 16640  (w2 padded)
#define SM_B1    16640                  // 64 -> 16704
#define SM_B2    16704                  // 36 -> 16740
#define SM_SIG   16740                  // 192 -> 16932
#define SM_Z     16932                  // 192 -> 17124
#define SM_TOTALF 17124                 // 68496 bytes

// Static scratch
__device__ float g_planesT[6 * PLSTRIDE];           // 50.3 MB
__device__ float g_rgb_c[(size_t)NSAMP * CRGB];     // 50.3 MB
__device__ float g_zf[NSAMP];

__device__ __forceinline__ float softplus_f(float x) {
    return fmaxf(x, 0.f) + __logf(1.f + __expf(-fabsf(x)));
}
__device__ __forceinline__ float sigmoid_f(float x) {
    return 1.f / (1.f + __expf(-x));
}
__device__ __forceinline__ float zc_depth(int i) {
    return RAY_START_F + ((float)i + 0.5f) * DELTA_F;
}

// ---------------------------------------------------------------------------
// K0: tiled transpose per plane
// ---------------------------------------------------------------------------
__global__ void transpose_planes_kernel(const float* __restrict__ in) {
    __shared__ float tile[32][33];
    int p = blockIdx.y;
    int hw0 = blockIdx.x * 32;
    int tx = threadIdx.x, ty = threadIdx.y;
    const float* ip = in + (size_t)p * CPL * (HPX * HPX);
    float* op = g_planesT + (size_t)p * PLSTRIDE;
    #pragma unroll
    for (int c = ty; c < 32; c += 8)
        tile[c][tx] = ip[(size_t)c * (HPX * HPX) + hw0 + tx];
    __syncthreads();
    #pragma unroll
    for (int r = ty; r < 32; r += 8)
        op[(size_t)(hw0 + r) * 32 + tx] = tile[tx][r];
}

// ---------------------------------------------------------------------------
// K1/K2 fused eval
// ---------------------------------------------------------------------------
template <int PASS>
__global__ __launch_bounds__(192, 3)
void eval_kernel(const float* __restrict__ origins,
                 const float* __restrict__ dirs,
                 const float* __restrict__ w1, const float* __restrict__ b1,
                 const float* __restrict__ w2, const float* __restrict__ b2,
                 float* __restrict__ out) {
    extern __shared__ float smem[];
    float* s_buf = smem + SM_BUF;
    float* s_gp  = smem + SM_GP;
    float* s_w1t = smem + SM_W1T;
    float* s_w2  = smem + SM_W2;
    float* s_b1  = smem + SM_B1;
    float* s_b2  = smem + SM_B2;
    float* s_sig = smem + SM_SIG;
    float* s_z   = smem + SM_Z;

    const int tid = threadIdx.x;
    const int lane = tid & 31;
    const int warp = tid >> 5;
    const unsigned FULL = 0xffffffffu;

    // ---- weight prep: w1 transposed j-major and pre-scaled by 1/3 (feat is
    //      a sum of 3 plane samples; mean folded into w1), w2 padded to 36 ----
    for (int i = tid; i < HID * CPL; i += 192) {
        int j = i >> 5, c = i & 31;
        s_w1t[i] = w1[c * HID + j] * (1.f / 3.f);
    }
    for (int i = tid; i < HID * 36; i += 192) {
        int j = i / 36, k = i - j * 36;
        s_w2[i] = (k < 33) ? w2[j * 33 + k] : 0.f;
    }
    if (tid < HID) s_b1[tid] = b1[tid];
    if (tid < 36) s_b2[tid] = (tid < 33) ? b2[tid] : 0.f;

    // ---- phase A: per-sample coords -> 12 (offset,weight) corner params ----
    const int gs = blockIdx.x * 192 + tid;
    const int rayLocal = tid / 48;
    const int samp = tid - rayLocal * 48;
    const int ray = blockIdx.x * 4 + rayLocal;

    float tz;
    if (PASS == 0) tz = zc_depth(samp);
    else tz = __ldg(&g_zf[gs]);
    s_z[tid] = tz;

    {
        float ox = __ldg(&origins[ray * 3 + 0]);
        float oy = __ldg(&origins[ray * 3 + 1]);
        float oz = __ldg(&origins[ray * 3 + 2]);
        float dx = __ldg(&dirs[ray * 3 + 0]);
        float dy = __ldg(&dirs[ray * 3 + 1]);
        float dz = __ldg(&dirs[ray * 3 + 2]);
        float X = fmaf(tz, dx, ox), Y = fmaf(tz, dy, oy), Z = fmaf(tz, dz, oz);
        int bb = ray >> 12;
        #pragma unroll
        for (int p = 0; p < 3; p++) {
            float u = (p == 2) ? Z : X;
            float v = (p == 0) ? Y : (p == 1) ? Z : X;
            float x = fmaf(u, 128.f, 127.5f);
            float y = fmaf(v, 128.f, 127.5f);
            float x0f = floorf(x), y0f = floorf(y);
            float fx = x - x0f, fy = y - y0f;
            int xi0 = min(max((int)x0f, 0), 255);
            int xi1 = min(max((int)x0f + 1, 0), 255);
            int yi0 = min(max((int)y0f, 0), 255);
            int yi1 = min(max((int)y0f + 1, 0), 255);
            float wx0 = (x0f >= 0.f && x0f < 256.f) ? (1.f - fx) : 0.f;
            float wx1 = (x0f + 1.f >= 0.f && x0f + 1.f < 256.f) ? fx : 0.f;
            float wy0 = (y0f >= 0.f && y0f < 256.f) ? (1.f - fy) : 0.f;
            float wy1 = (y0f + 1.f >= 0.f && y0f + 1.f < 256.f) ? fy : 0.f;
            int base = (bb * 3 + p) * PLSTRIDE;
            int o0 = base + yi0 * (HPX * CPL);
            int o1 = base + yi1 * (HPX * CPL);
            float2* gp = reinterpret_cast<float2*>(s_gp + tid * 24 + p * 8);
            gp[0] = make_float2(__int_as_float(o0 + xi0 * CPL), wy0 * wx0);
            gp[1] = make_float2(__int_as_float(o0 + xi1 * CPL), wy0 * wx1);
            gp[2] = make_float2(__int_as_float(o1 + xi0 * CPL), wy1 * wx0);
            gp[3] = make_float2(__int_as_float(o1 + xi1 * CPL), wy1 * wx1);
        }
    }
    __syncthreads();

    // ---- gather: warp-cooperative, lane = corner(2b) x chunk(3b), scalar ----
    {
        const int corner = lane >> 3;
        const int chunk = lane & 7;
        for (int i = 0; i < 32; i++) {
            int s = (warp << 5) + i;
            float ax = 0.f, ay = 0.f, az = 0.f, aw = 0.f;
            #pragma unroll
            for (int p = 0; p < 3; p++) {
                float2 pw = *reinterpret_cast<const float2*>(
                    s_gp + s * 24 + p * 8 + corner * 2);
                int off = __float_as_int(pw.x);
                float w = pw.y;
                float4 v = __ldg(
                    reinterpret_cast<const float4*>(g_planesT + off) + chunk);
                ax = fmaf(v.x, w, ax);
                ay = fmaf(v.y, w, ay);
                az = fmaf(v.z, w, az);
                aw = fmaf(v.w, w, aw);
            }
            ax += __shfl_xor_sync(FULL, ax, 8);
            ay += __shfl_xor_sync(FULL, ay, 8);
            az += __shfl_xor_sync(FULL, az, 8);
            aw += __shfl_xor_sync(FULL, aw, 8);
            ax += __shfl_xor_sync(FULL, ax, 16);
            ay += __shfl_xor_sync(FULL, ay, 16);
            az += __shfl_xor_sync(FULL, az, 16);
            aw += __shfl_xor_sync(FULL, aw, 16);
            if (lane < 8) {
                *reinterpret_cast<float4*>(s_buf + s * BUFS + chunk * 4) =
                    make_float4(ax, ay, az, aw);
            }
        }
    }
    __syncwarp();

    // ---- MLP: thread = sample; scalar FFMA, float4 broadcast weight LDS ----
    float feat[CPL];
    {
        const float4* f4 = reinterpret_cast<const float4*>(s_buf + tid * BUFS);
        #pragma unroll
        for (int k = 0; k < 8; k++) {
            float4 v = f4[k];
            feat[4 * k + 0] = v.x; feat[4 * k + 1] = v.y;
            feat[4 * k + 2] = v.z; feat[4 * k + 3] = v.w;
        }
    }
    float acc[36];
    #pragma unroll
    for (int k = 0; k < 36; k++) acc[k] = s_b2[k];
    {
        const float4* w1t4 = reinterpret_cast<const float4*>(s_w1t);
        const float4* w24 = reinterpret_cast<const float4*>(s_w2);
        #pragma unroll 4
        for (int j = 0; j < HID; j++) {
            float h = s_b1[j];
            #pragma unroll
            for (int cc = 0; cc < 8; cc++) {
                float4 wv = w1t4[j * 8 + cc];
                h = fmaf(feat[4 * cc + 0], wv.x, h);
                h = fmaf(feat[4 * cc + 1], wv.y, h);
                h = fmaf(feat[4 * cc + 2], wv.z, h);
                h = fmaf(feat[4 * cc + 3], wv.w, h);
            }
            h = softplus_f(h);
            #pragma unroll
            for (int kk = 0; kk < 9; kk++) {
                float4 wv = w24[j * 9 + kk];
                acc[4 * kk + 0] = fmaf(h, wv.x, acc[4 * kk + 0]);
                acc[4 * kk + 1] = fmaf(h, wv.y, acc[4 * kk + 1]);
                acc[4 * kk + 2] = fmaf(h, wv.z, acc[4 * kk + 2]);
                acc[4 * kk + 3] = fmaf(h, wv.w, acc[4 * kk + 3]);
            }
        }
    }
    // ---- epilogue: sigma + rgb (own s_buf row) ----
    s_sig[tid] = acc[0];
    if (PASS == 0) out[OFF_SDF + gs] = acc[0];
    #pragma unroll
    for (int k = 0; k < CRGB; k++)
        s_buf[tid * BUFS + k] = sigmoid_f(acc[1 + k]) * 1.002f - 0.001f;
    __syncthreads();

    if (PASS == 0) {
        // coalesced rgb_c store
        size_t ob = (size_t)blockIdx.x * 192 * CRGB;
        for (int i = tid; i < 192 * CRGB; i += 192) {
            int sm = i >> 5, k = i & 31;
            g_rgb_c[ob + i] = s_buf[sm * BUFS + k];
        }
        // fused importance sampling: thread r handles ray r
        if (tid < 4) {
            const float* sg = s_sig + tid * SC;
            int rayO = blockIdx.x * 4 + tid;
            float w[SC - 1];
            float T = 1.f;
            float prev = sg[0];
            for (int i = 0; i < SC - 1; i++) {
                float cur = sg[i + 1];
                float dens = softplus_f(0.5f * (prev + cur) - 1.f);
                float a = 1.f - __expf(-dens * DELTA_F);
                w[i] = a * T;
                T *= (1.f - a + 1e-10f);
                prev = cur;
            }
            float pw[45];
            float sum = 0.f;
            for (int i = 1; i <= 45; i++) {
                float wp_i = w[i - 1];
                float wp_i1 = w[i];
                float wp_i2 = (i + 2 <= 47) ? w[i + 1] : 0.f;
                float wm0 = fmaxf(wp_i, wp_i1);
                float wm1 = fmaxf(wp_i1, wp_i2);
                float val = 0.5f * (wm0 + wm1) + 0.01f;
                pw[i - 1] = val;
                sum += val;
            }
            float cdf[46];
            cdf[0] = 0.f;
            for (int i = 0; i < 45; i++) cdf[i + 1] = cdf[i] + pw[i] / sum;
            int idx = 0;
            for (int j = 0; j < SF; j++) {
                float u = (float)j / 47.0f;
                while (idx < 46 && cdf[idx] <= u) idx++;
                int below = idx - 1;
                below = below < 0 ? 0 : (below > 45 ? 45 : below);
                int above = idx > 45 ? 45 : idx;
                float cb = cdf[below], ca = cdf[above];
                float bbv = 0.5f * (zc_depth(below) + zc_depth(below + 1));
                float bav = 0.5f * (zc_depth(above) + zc_depth(above + 1));
                float d = ca - cb;
                float denom = (d < 1e-5f) ? 1.f : d;
                g_zf[(size_t)rayO * SF + j] = bbv + (u - cb) / denom * (bav - bbv);
            }
        }
    } else {
        // fused merge + final ray march: warp wr (<4) handles ray wr
        if (warp < 4) {
            int rayO = blockIdx.x * 4 + warp;
            const float* sdfc = out + OFF_SDF + (size_t)rayO * SC;
            const float* zf = s_z + warp * SF;
            const float* sf = s_sig + warp * SF;
            int ic = 0, ifn = 0;
            float T = 1.f, rgb_acc = 0.f, dep = 0.f, ws = 0.f;
            float zp, sp2, cp;
            {
                bool tc = (zc_depth(0) <= zf[0]);
                if (tc) {
                    zp = zc_depth(0); sp2 = __ldg(&sdfc[0]);
                    cp = __ldg(&g_rgb_c[((size_t)rayO * SC) * CRGB + lane]);
                    ic = 1;
                } else {
                    zp = zf[0]; sp2 = sf[0];
                    cp = s_buf[(warp * SF) * BUFS + lane];
                    ifn = 1;
                }
            }
            for (int i = 1; i < SC + SF; i++) {
                bool tc = (ic < SC) && (ifn >= SF || zc_depth(ic) <= zf[ifn]);
                float z, sgv, cc;
                if (tc) {
                    z = zc_depth(ic); sgv = __ldg(&sdfc[ic]);
                    cc = __ldg(&g_rgb_c[((size_t)rayO * SC + ic) * CRGB + lane]);
                    ic++;
                } else {
                    z = zf[ifn]; sgv = sf[ifn];
                    cc = s_buf[(warp * SF + ifn) * BUFS + lane];
                    ifn++;
                }
                float delta = z - zp;
                float cmid = 0.5f * (cp + cc);
                float smid = softplus_f(0.5f * (sp2 + sgv) - 1.f);
                float a = 1.f - __expf(-smid * delta);
                float wgt = a * T;
                T *= (1.f - a + 1e-10f);
                rgb_acc = fmaf(wgt, cmid, rgb_acc);
                dep = fmaf(wgt, 0.5f * (zp + z), dep);
                ws += wgt;
                zp = z; sp2 = sgv; cp = cc;
            }
            out[(size_t)rayO * CRGB + lane] = rgb_acc * 2.f - 1.f;
            if (lane == 0) {
                out[OFF_DEPTH + rayO] = dep;
                out[OFF_WSUM + rayO] = ws;
            }
        }
    }
}

// ---------------------------------------------------------------------------
extern "C" void kernel_launch(void* const* d_in, const int* in_sizes, int n_in,
                              void* d_out, int out_size) {
    const float* planes = (const float*)d_in[0];
    const float* org    = (const float*)d_in[1];
    const float* dir    = (const float*)d_in[2];
    const float* w1     = (const float*)d_in[3];
    const float* b1     = (const float*)d_in[4];
    const float* w2     = (const float*)d_in[5];
    const float* b2     = (const float*)d_in[6];
    float* out = (float*)d_out;

    const int smem_bytes = SM_TOTALF * sizeof(float);
    cudaFuncSetAttribute(eval_kernel<0>, cudaFuncAttributeMaxDynamicSharedMemorySize, smem_bytes);
    cudaFuncSetAttribute(eval_kernel<1>, cudaFuncAttributeMaxDynamicSharedMemorySize, smem_bytes);

    {
        dim3 tb(32, 8), tg(HPX * HPX / 32, 6);
        transpose_planes_kernel<<<tg, tb>>>(planes);
    }
    eval_kernel<0><<<NRAY / 4, 192, smem_bytes>>>(org, dir, w1, b1, w2, b2, out);
    eval_kernel<1><<<NRAY / 4, 192, smem_bytes>>>(org, dir, w1, b1, w2, b2, out);
}

// round 14
// speedup vs baseline: 1.2776x; 1.2776x over previous
#include <cuda_runtime.h>
#include <math.h>
#include <stdint.h>

// ---------------------------------------------------------------------------
// ImportanceRenderer, R2 architecture + micro-opts (scalar FFMA only; this
// target compiles as plain sm_100: no tcgen05, no f32x2, warp-MMA crippled).
//  K0: transpose planes -> channel-last
//  K1: eval<0> coarse   K2: importance   K3: eval<1> fine   K4: finalize
// eval block = 128 threads = 128 samples; warp-tile = 32 samples, lane=channel.
// ---------------------------------------------------------------------------

#define B_N 2
#define R_N 4096
#define SC 48
#define SF 48
#define NRAY (B_N * R_N)        // 8192
#define NSAMP (NRAY * SC)       // 393216
#define CPL 32
#define HPX 256
#define HID 64
#define CRGB 32
#define PLSTRIDE (HPX * HPX * CPL)

#define RAY_START_F 2.25f
#define DELTA_F (1.05f / 47.0f)

#define OFF_DEPTH (NRAY * CRGB)
#define OFF_WSUM  (OFF_DEPTH + NRAY)
#define OFF_SDF   (OFF_WSUM + NRAY)

// Static scratch
__device__ float g_planesT[6 * PLSTRIDE];           // 50.3 MB
__device__ float g_rgb_c[(size_t)NSAMP * CRGB];     // 50.3 MB
__device__ float g_rgb_f[(size_t)NSAMP * CRGB];     // 50.3 MB
__device__ float g_sig_f[NSAMP];
__device__ float g_zf[NSAMP];

__device__ __forceinline__ float softplus_f(float x) {
    return fmaxf(x, 0.f) + __logf(1.f + __expf(-fabsf(x)));
}
__device__ __forceinline__ float sigmoid_f(float x) {
    return __fdividef(1.f, 1.f + __expf(-x));
}
__device__ __forceinline__ float zc_depth(int i) {
    return RAY_START_F + ((float)i + 0.5f) * DELTA_F;
}

// 1-D bilinear axis solve: clamped indices + validity-masked weights.
__device__ __forceinline__ void solve_axis(float u, int& i0, int& i1,
                                           float& w0, float& w1) {
    float x = fmaf(u, 128.f, 127.5f);   // ((u+1)*256-1)*0.5
    float x0f = floorf(x);
    float fx = x - x0f;
    i0 = min(max((int)x0f, 0), 255);
    i1 = min(max((int)x0f + 1, 0), 255);
    w0 = (x0f >= 0.f && x0f < 256.f) ? (1.f - fx) : 0.f;
    w1 = (x0f >= -1.f && x0f < 255.f) ? fx : 0.f;
}

// ---------------------------------------------------------------------------
// K0: tiled transpose per plane
// ---------------------------------------------------------------------------
__global__ void transpose_planes_kernel(const float* __restrict__ in) {
    __shared__ float tile[32][33];
    int p = blockIdx.y;
    int hw0 = blockIdx.x * 32;
    int tx = threadIdx.x, ty = threadIdx.y;
    const float* ip = in + (size_t)p * CPL * (HPX * HPX);
    float* op = g_planesT + (size_t)p * PLSTRIDE;
    #pragma unroll
    for (int c = ty; c < 32; c += 8)
        tile[c][tx] = ip[(size_t)c * (HPX * HPX) + hw0 + tx];
    __syncthreads();
    #pragma unroll
    for (int r = ty; r < 32; r += 8)
        op[(size_t)(hw0 + r) * 32 + tx] = tile[tx][r];
}

// ---------------------------------------------------------------------------
// K1/K3: eval. PASS=0 coarse (sigma->out sdf region), PASS=1 fine.
// ---------------------------------------------------------------------------
template <int PASS>
__global__ __launch_bounds__(128)
void eval_kernel(const float* __restrict__ origins,
                 const float* __restrict__ dirs,
                 const float* __restrict__ w1, const float* __restrict__ b1,
                 const float* __restrict__ w2, const float* __restrict__ b2,
                 float* __restrict__ sig_out_coarse) {
    __shared__ __align__(16) float s_w1t[HID * CPL];   // [j][c], pre-scaled 1/3
    __shared__ __align__(16) float s_w2[HID * 36];     // [j][k], padded to 36
    __shared__ float s_b1[HID];
    __shared__ float s_b2[36];
    __shared__ float s_feat[128 * 33];

    int tid = threadIdx.x;
    for (int i = tid; i < HID * CPL; i += 128) {
        int j = i >> 5, c = i & 31;
        s_w1t[i] = w1[c * HID + j] * (1.f / 3.f);      // fold plane-mean
    }
    for (int i = tid; i < HID * 36; i += 128) {
        int j = i / 36, k = i - j * 36;
        s_w2[i] = (k < 33) ? w2[j * 33 + k] : 0.f;
    }
    if (tid < HID) s_b1[tid] = b1[tid];
    if (tid < 36) s_b2[tid] = (tid < 33) ? b2[tid] : 0.f;

    int lane = tid & 31;
    int warp = tid >> 5;
    int base_sample = blockIdx.x * 128 + warp * 32;

    // ---- Gather: 32 samples/warp, lane = channel; unique-axis solves ----
    for (int s = 0; s < 32; s++) {
        int gs = base_sample + s;
        int samp = gs % SC;
        int ray = gs / SC;
        float t;
        if (PASS == 0) t = zc_depth(samp);
        else t = __ldg(&g_zf[gs]);
        float ox = __ldg(&origins[ray * 3 + 0]);
        float oy = __ldg(&origins[ray * 3 + 1]);
        float oz = __ldg(&origins[ray * 3 + 2]);
        float dx = __ldg(&dirs[ray * 3 + 0]);
        float dy = __ldg(&dirs[ray * 3 + 1]);
        float dz = __ldg(&dirs[ray * 3 + 2]);
        float X = fmaf(t, dx, ox), Y = fmaf(t, dy, oy), Z = fmaf(t, dz, oz);
        int bb = ray >> 12;
        const float* pb = g_planesT + (size_t)(bb * 3) * PLSTRIDE;

        // solve each axis once; planes: (X,Y), (X,Z), (Z,X)
        int xi0, xi1, yi0, yi1, zi0, zi1;
        float xw0, xw1, yw0, yw1, zw0, zw1;
        solve_axis(X, xi0, xi1, xw0, xw1);
        solve_axis(Y, yi0, yi1, yw0, yw1);
        solve_axis(Z, zi0, zi1, zw0, zw1);

        int cX0 = xi0 * CPL + lane, cX1 = xi1 * CPL + lane;
        int cZ0 = zi0 * CPL + lane, cZ1 = zi1 * CPL + lane;
        int rX0 = xi0 * (HPX * CPL), rX1 = xi1 * (HPX * CPL);
        int rY0 = yi0 * (HPX * CPL), rY1 = yi1 * (HPX * CPL);
        int rZ0 = zi0 * (HPX * CPL), rZ1 = zi1 * (HPX * CPL);

        float acc;
        {   // plane 0: u=X (cols), v=Y (rows)
            const float* p0 = pb;
            float v00 = __ldg(p0 + rY0 + cX0);
            float v01 = __ldg(p0 + rY0 + cX1);
            float v10 = __ldg(p0 + rY1 + cX0);
            float v11 = __ldg(p0 + rY1 + cX1);
            float r0 = fmaf(v01, xw1, v00 * xw0);
            float r1 = fmaf(v11, xw1, v10 * xw0);
            acc = fmaf(r1, yw1, r0 * yw0);
        }
        {   // plane 1: u=X (cols), v=Z (rows)
            const float* p1 = pb + PLSTRIDE;
            float v00 = __ldg(p1 + rZ0 + cX0);
            float v01 = __ldg(p1 + rZ0 + cX1);
            float v10 = __ldg(p1 + rZ1 + cX0);
            float v11 = __ldg(p1 + rZ1 + cX1);
            float r0 = fmaf(v01, xw1, v00 * xw0);
            float r1 = fmaf(v11, xw1, v10 * xw0);
            acc = fmaf(r1, zw1, fmaf(r0, zw0, acc));
        }
        {   // plane 2: u=Z (cols), v=X (rows)
            const float* p2 = pb + 2 * PLSTRIDE;
            float v00 = __ldg(p2 + rX0 + cZ0);
            float v01 = __ldg(p2 + rX0 + cZ1);
            float v10 = __ldg(p2 + rX1 + cZ0);
            float v11 = __ldg(p2 + rX1 + cZ1);
            float r0 = fmaf(v01, zw1, v00 * zw0);
            float r1 = fmaf(v11, zw1, v10 * zw0);
            acc = fmaf(r1, xw1, fmaf(r0, xw0, acc));
        }
        s_feat[(warp * 32 + s) * 33 + lane] = acc;     // 1/3 folded into w1
    }
    __syncthreads();

    // ---- MLP: thread = sample; 4-partial h accumulation ----
    float feat[CPL];
    #pragma unroll
    for (int c = 0; c < CPL; c++) feat[c] = s_feat[tid * 33 + c];
    float acc[36];
    #pragma unroll
    for (int k = 0; k < 36; k++) acc[k] = s_b2[k];
    const float4* w1t4 = reinterpret_cast<const float4*>(s_w1t);
    const float4* w24 = reinterpret_cast<const float4*>(s_w2);
    #pragma unroll 2
    for (int j = 0; j < HID; j++) {
        float p0 = s_b1[j], p1 = 0.f, p2 = 0.f, p3 = 0.f;
        #pragma unroll
        for (int cc = 0; cc < 8; cc++) {
            float4 wv = w1t4[j * 8 + cc];
            p0 = fmaf(feat[4 * cc + 0], wv.x, p0);
            p1 = fmaf(feat[4 * cc + 1], wv.y, p1);
            p2 = fmaf(feat[4 * cc + 2], wv.z, p2);
            p3 = fmaf(feat[4 * cc + 3], wv.w, p3);
        }
        float h = softplus_f((p0 + p1) + (p2 + p3));
        #pragma unroll
        for (int kk = 0; kk < 9; kk++) {
            float4 wv = w24[j * 9 + kk];
            acc[4 * kk + 0] = fmaf(h, wv.x, acc[4 * kk + 0]);
            acc[4 * kk + 1] = fmaf(h, wv.y, acc[4 * kk + 1]);
            acc[4 * kk + 2] = fmaf(h, wv.z, acc[4 * kk + 2]);
            acc[4 * kk + 3] = fmaf(h, wv.w, acc[4 * kk + 3]);
        }
    }
    int gid = blockIdx.x * 128 + tid;
    if (PASS == 0) sig_out_coarse[gid] = acc[0];
    else g_sig_f[gid] = acc[0];

    __syncthreads();  // safe to reuse s_feat
    #pragma unroll
    for (int k = 0; k < CRGB; k++)
        s_feat[tid * 33 + k] = sigmoid_f(acc[1 + k]) * 1.002f - 0.001f;
    __syncthreads();
    float* ro = (PASS == 0) ? g_rgb_c : g_rgb_f;
    size_t ob = (size_t)blockIdx.x * 128 * CRGB;
    for (int i = tid; i < 128 * CRGB; i += 128) {
        int sm = i >> 5, k = i & 31;
        ro[ob + i] = s_feat[sm * 33 + k];
    }
}

// ---------------------------------------------------------------------------
// K2: per-ray coarse march -> smoothed PDF -> inverse-CDF sampling.
// ---------------------------------------------------------------------------
__global__ void importance_kernel(const float* __restrict__ sdf) {
    int ray = blockIdx.x * blockDim.x + threadIdx.x;
    if (ray >= NRAY) return;
    const float* sg = sdf + (size_t)ray * SC;

    float w[SC - 1];
    float T = 1.f;
    float prev = __ldg(&sg[0]);
    for (int i = 0; i < SC - 1; i++) {
        float cur = __ldg(&sg[i + 1]);
        float dens = softplus_f(0.5f * (prev + cur) - 1.f);
        float a = 1.f - __expf(-dens * DELTA_F);
        w[i] = a * T;
        T *= (1.f - a + 1e-10f);
        prev = cur;
    }
    float pw[45];
    float sum = 0.f;
    for (int i = 1; i <= 45; i++) {
        float wp_i = w[i - 1];
        float wp_i1 = w[i];
        float wp_i2 = (i + 2 <= 47) ? w[i + 1] : 0.f;
        float wm0 = fmaxf(wp_i, wp_i1);
        float wm1 = fmaxf(wp_i1, wp_i2);
        float val = 0.5f * (wm0 + wm1) + 0.01f;
        pw[i - 1] = val;
        sum += val;
    }
    float cdf[46];
    cdf[0] = 0.f;
    for (int i = 0; i < 45; i++) cdf[i + 1] = cdf[i] + pw[i] / sum;
    int idx = 0;
    for (int j = 0; j < SF; j++) {
        float u = (float)j / 47.0f;
        while (idx < 46 && cdf[idx] <= u) idx++;
        int below = idx - 1;
        below = below < 0 ? 0 : (below > 45 ? 45 : below);
        int above = idx > 45 ? 45 : idx;
        float cb = cdf[below], ca = cdf[above];
        float bbv = 0.5f * (zc_depth(below) + zc_depth(below + 1));
        float bav = 0.5f * (zc_depth(above) + zc_depth(above + 1));
        float d = ca - cb;
        float denom = (d < 1e-5f) ? 1.f : d;
        g_zf[(size_t)ray * SF + j] = bbv + (u - cb) / denom * (bav - bbv);
    }
}

// ---------------------------------------------------------------------------
// K4: per-ray merge of sorted coarse + fine, final 96-sample march.
// ---------------------------------------------------------------------------
__global__ __launch_bounds__(128)
void finalize_kernel(const float* __restrict__ sdfc, float* __restrict__ out) {
    __shared__ float s_zf[4][SF], s_sc[4][SC], s_sf[4][SF];
    int lane = threadIdx.x & 31;
    int wp = threadIdx.x >> 5;
    int ray = blockIdx.x * 4 + wp;
    for (int i = lane; i < SC; i += 32) {
        s_zf[wp][i] = g_zf[(size_t)ray * SF + i];
        s_sc[wp][i] = sdfc[(size_t)ray * SC + i];
        s_sf[wp][i] = g_sig_f[(size_t)ray * SF + i];
    }
    __syncwarp();

    int ic = 0, ifn = 0;
    float T = 1.f, rgb_acc = 0.f, dep = 0.f, ws = 0.f;
    float zp, sp2, cp;
    {
        bool tc = (zc_depth(0) <= s_zf[wp][0]);
        if (tc) {
            zp = zc_depth(0); sp2 = s_sc[wp][0];
            cp = __ldg(&g_rgb_c[((size_t)ray * SC + 0) * CRGB + lane]);
            ic = 1;
        } else {
            zp = s_zf[wp][0]; sp2 = s_sf[wp][0];
            cp = __ldg(&g_rgb_f[((size_t)ray * SF + 0) * CRGB + lane]);
            ifn = 1;
        }
    }
    for (int i = 1; i < SC + SF; i++) {
        bool tc = (ic < SC) && (ifn >= SF || zc_depth(ic) <= s_zf[wp][ifn]);
        float z, sgv, cc;
        if (tc) {
            z = zc_depth(ic); sgv = s_sc[wp][ic];
            cc = __ldg(&g_rgb_c[((size_t)ray * SC + ic) * CRGB + lane]);
            ic++;
        } else {
            z = s_zf[wp][ifn]; sgv = s_sf[wp][ifn];
            cc = __ldg(&g_rgb_f[((size_t)ray * SF + ifn) * CRGB + lane]);
            ifn++;
        }
        float delta = z - zp;
        float cmid = 0.5f * (cp + cc);
        float smid = softplus_f(0.5f * (sp2 + sgv) - 1.f);
        float a = 1.f - __expf(-smid * delta);
        float wgt = a * T;
        T *= (1.f - a + 1e-10f);
        rgb_acc = fmaf(wgt, cmid, rgb_acc);
        dep = fmaf(wgt, 0.5f * (zp + z), dep);
        ws += wgt;
        zp = z; sp2 = sgv; cp = cc;
    }
    out[(size_t)ray * CRGB + lane] = rgb_acc * 2.f - 1.f;
    if (lane == 0) {
        out[OFF_DEPTH + ray] = dep;
        out[OFF_WSUM + ray] = ws;
    }
}

// ---------------------------------------------------------------------------
extern "C" void kernel_launch(void* const* d_in, const int* in_sizes, int n_in,
                              void* d_out, int out_size) {
    const float* planes = (const float*)d_in[0];
    const float* org    = (const float*)d_in[1];
    const float* dir    = (const float*)d_in[2];
    const float* w1     = (const float*)d_in[3];
    const float* b1     = (const float*)d_in[4];
    const float* w2     = (const float*)d_in[5];
    const float* b2     = (const float*)d_in[6];
    float* out = (float*)d_out;

    {
        dim3 tb(32, 8), tg(HPX * HPX / 32, 6);
        transpose_planes_kernel<<<tg, tb>>>(planes);
    }
    eval_kernel<0><<<NSAMP / 128, 128>>>(org, dir, w1, b1, w2, b2, out + OFF_SDF);
    importance_kernel<<<(NRAY + 127) / 128, 128>>>(out + OFF_SDF);
    eval_kernel<1><<<NSAMP / 128, 128>>>(org, dir, w1, b1, w2, b2, nullptr);
    finalize_kernel<<<NRAY / 4, 128>>>(out + OFF_SDF, out);
}